// round 14
// baseline (speedup 1.0000x reference)
#include <cuda_runtime.h>
#include <stdint.h>
#include <math.h>

#define BATCH 32
#define CHAN  256
#define HH    56
#define WW    56
#define S     (HH*WW)        // 3136
#define S4    (S/4)          // 784
#define QSPLIT 8
#define CQ    (CHAN/QSPLIT)  // 32
#define RNUM  1568           // removed_num = round(3136*0.5)
#define MBLK  4              // mid blocks per batch
#define RPB   (HH/MBLK)      // 14 output rows per mid block

// scratch (no cudaMalloc allowed)
__device__ __align__(16) float        g_part_max[QSPLIT*BATCH*S];
__device__ __align__(16) float        g_part_sum[QSPLIT*BATCH*S];
__device__ __align__(16) unsigned int g_uvals[BATCH*S];
__device__ __align__(16) float        g_y[BATCH*S];
__device__ int g_hist[BATCH*256];   // zero-init; consumer resets after read
__device__ int g_cnt[BATCH];        // zero-init; consumer resets after election

// ---------------------------------------------------------------------------
// Kernel 1: partial channel max/sum. 784 blocks x 256 threads, QSPLIT=8.
// (Measured best: 19.3us @ 70% DRAM.)
// ---------------------------------------------------------------------------
__global__ void pool_partial(const float* __restrict__ x) {
    int gid = blockIdx.x * blockDim.x + threadIdx.x;
    int q   = gid / (BATCH * S4);
    int rem = gid % (BATCH * S4);
    int b   = rem / S4;
    int s4  = rem % S4;

    const float4* p = reinterpret_cast<const float4*>(x)
                    + (size_t)(b * CHAN + q * CQ) * S4 + s4;

    float4 mx = make_float4(-INFINITY, -INFINITY, -INFINITY, -INFINITY);
    float4 sm = make_float4(0.f, 0.f, 0.f, 0.f);

    #pragma unroll 8
    for (int c = 0; c < CQ; ++c) {
        float4 v = __ldcs(p + (size_t)c * S4);   // read-once: stream past L2
        mx.x = fmaxf(mx.x, v.x); mx.y = fmaxf(mx.y, v.y);
        mx.z = fmaxf(mx.z, v.z); mx.w = fmaxf(mx.w, v.w);
        sm.x += v.x; sm.y += v.y; sm.z += v.z; sm.w += v.w;
    }

    int o = (q * BATCH + b) * S4 + s4;
    reinterpret_cast<float4*>(g_part_max)[o] = mx;
    reinterpret_cast<float4*>(g_part_sum)[o] = sm;
}

// ---------------------------------------------------------------------------
// Kernel 2 (parallel middle): 128 blocks (4/batch) x 1024 threads.
// Phase A (all blocks): combine 14-row slab (+halo) -> conv+sigmoid ->
//   g_uvals + pass-0 histogram merged into g_hist[b].
// Phase B (last block per batch): radix select passes (pass 0 from g_hist),
//   masked write to g_y. Counters/hists reset by consumer (replay-safe).
// ---------------------------------------------------------------------------
__global__ void __launch_bounds__(1024, 1) mid_par(const float* __restrict__ w) {
    __shared__ float pm[(RPB + 2) * WW];        // 16 rows x 56
    __shared__ float pa[(RPB + 2) * WW];
    __shared__ unsigned int uvals[S];           // used by elected block
    __shared__ int hist[256];
    __shared__ float ws[18];
    __shared__ unsigned int s_prefix;
    __shared__ int s_r, s_less;
    __shared__ int tieIdx[256];
    __shared__ int tieCount;
    __shared__ int amLast;

    const int b  = blockIdx.x / MBLK;
    const int qb = blockIdx.x % MBLK;
    const int t  = threadIdx.x;
    const int lane = t & 31;
    const int r0 = qb * RPB;                    // first output row

    if (t < 18) ws[t] = w[t];
    if (t < 256) hist[t] = 0;
    __syncthreads();

    // --- Phase A1: combine partials for rows r0-1 .. r0+RPB (16 rows) ---
    const float inv = 1.0f / (float)CHAN;
    const int W4 = WW / 4;                      // 14 float4 per row
    if (t < (RPB + 2) * W4) {                   // 224 items
        int lrow = t / W4;
        int c4   = t % W4;
        int grow = r0 - 1 + lrow;
        float4 mx = make_float4(0.f, 0.f, 0.f, 0.f);
        float4 sm = make_float4(0.f, 0.f, 0.f, 0.f);
        if (grow >= 0 && grow < HH) {
            int o4 = grow * W4 + c4;            // float4 index within batch map
            mx = make_float4(-INFINITY, -INFINITY, -INFINITY, -INFINITY);
            #pragma unroll
            for (int q = 0; q < QSPLIT; ++q) {
                int o = (q * BATCH + b) * S4 + o4;
                float4 m = reinterpret_cast<const float4*>(g_part_max)[o];
                float4 s = reinterpret_cast<const float4*>(g_part_sum)[o];
                mx.x = fmaxf(mx.x, m.x); mx.y = fmaxf(mx.y, m.y);
                mx.z = fmaxf(mx.z, m.z); mx.w = fmaxf(mx.w, m.w);
                sm.x += s.x; sm.y += s.y; sm.z += s.z; sm.w += s.w;
            }
            sm.x *= inv; sm.y *= inv; sm.z *= inv; sm.w *= inv;
        }
        reinterpret_cast<float4*>(pm)[t] = mx;  // zero rows act as conv padding
        reinterpret_cast<float4*>(pa)[t] = sm;
    }
    __syncthreads();

    // --- Phase A2: conv 3x3 + sigmoid; write g_uvals; local pass-0 hist ---
    if (t < RPB * WW) {                         // 784 outputs
        int ohl = t / WW;                       // 0..13
        int ow  = t % WW;
        int oh  = r0 + ohl;
        float acc = 0.f;
        #pragma unroll
        for (int ky = 0; ky < 3; ++ky) {
            int lr = ohl + ky;                  // smem row: (oh+ky-1)-(r0-1)
            #pragma unroll
            for (int kx = 0; kx < 3; ++kx) {
                int iw = ow + kx - 1;
                if (iw < 0 || iw >= WW) continue;
                int ii = lr * WW + iw;
                acc = fmaf(pm[ii], ws[ky * 3 + kx], acc);
                acc = fmaf(pa[ii], ws[9 + ky * 3 + kx], acc);
            }
        }
        unsigned int u = __float_as_uint(1.0f / (1.0f + expf(-acc)));
        g_uvals[b * S + oh * WW + ow] = u;
        atomicAdd(&hist[u >> 24], 1);
    }
    __syncthreads();

    // merge local pass-0 hist into per-batch global hist
    if (t < 256) atomicAdd(&g_hist[b * 256 + t], hist[t]);

    // --- election: last block of batch continues ---
    __threadfence();
    __syncthreads();
    if (t == 0) {
        int old = atomicAdd(&g_cnt[b], 1);
        amLast = (old == MBLK - 1);
        if (amLast) g_cnt[b] = 0;               // sole owner now: reset
    }
    __syncthreads();
    if (!amLast) return;
    __threadfence();                            // acquire peers' uvals/hist

    // --- Phase B: select over full batch ---
    if (t < 256) { hist[t] = g_hist[b * 256 + t]; g_hist[b * 256 + t] = 0; }
    if (t == 0) { s_r = RNUM - 1; s_less = 0; s_prefix = 0u; tieCount = 0; }
    for (int i = t; i < S; i += 1024) uvals[i] = g_uvals[b * S + i];
    __syncthreads();

    #pragma unroll
    for (int pass = 0; pass < 4; ++pass) {
        const int shift = 24 - 8 * pass;

        if (pass > 0) {
            const unsigned int pmask = 0xFFFFFFFFu << (32 - 8 * pass);
            const unsigned int pref  = s_prefix;
            for (int i = t; i < S; i += 1024) {
                unsigned int u = uvals[i];
                if ((u & pmask) == pref)
                    atomicAdd(&hist[(u >> shift) & 0xFF], 1);
            }
            __syncthreads();
        }

        if (t < 32) {                           // warp-0 bin scan + select
            int base = t * 8;
            int h0 = hist[base + 0], h1 = hist[base + 1];
            int h2 = hist[base + 2], h3 = hist[base + 3];
            int h4 = hist[base + 4], h5 = hist[base + 5];
            int h6 = hist[base + 6], h7 = hist[base + 7];
            int tot = h0 + h1 + h2 + h3 + h4 + h5 + h6 + h7;

            int ex = tot;                       // exclusive prefix of lane totals
            #pragma unroll
            for (int d = 1; d < 32; d <<= 1) {
                int n = __shfl_up_sync(0xFFFFFFFFu, ex, d);
                if (lane >= d) ex += n;
            }
            ex -= tot;

            int r = s_r;
            if (ex <= r && r < ex + tot) {      // exactly one lane matches
                int cum = ex, bin = base;
                int hh[8] = {h0,h1,h2,h3,h4,h5,h6,h7};
                #pragma unroll
                for (int k = 0; k < 8; ++k) {
                    if (cum + hh[k] > r) { bin = base + k; break; }
                    cum += hh[k];
                }
                s_r      = r - cum;
                s_less  += cum;
                s_prefix = (pass == 0 ? 0u : s_prefix) | ((unsigned int)bin << shift);
            }
        }
        __syncthreads();

        if (pass < 3) {
            if (t < 256) hist[t] = 0;
            __syncthreads();
        }
    }

    const unsigned int T = s_prefix;
    const int zeroTies = RNUM - s_less;         // # ties (==T) to zero, ascending index

    float* yb = g_y + b * S;
    for (int i = t; i < S; i += 1024) {
        unsigned int u = uvals[i];
        float v = __uint_as_float(u);
        if (u < T) v = 0.0f;
        else if (u == T) {
            int p = atomicAdd(&tieCount, 1);
            if (p < 256) tieIdx[p] = i;
        }
        yb[i] = v;                              // ties fixed below
    }
    __syncthreads();

    if (t == 0) {
        int tc = tieCount < 256 ? tieCount : 256;
        for (int i = 1; i < tc; ++i) {          // expected tc == 1
            int v2 = tieIdx[i], j = i - 1;
            while (j >= 0 && tieIdx[j] > v2) { tieIdx[j + 1] = tieIdx[j]; --j; }
            tieIdx[j + 1] = v2;
        }
        int z = zeroTies < tc ? zeroTies : tc;
        for (int j = 0; j < z; ++j) yb[tieIdx[j]] = 0.0f;
    }
}

// ---------------------------------------------------------------------------
// Kernel 3: broadcast masked map to all 256 channels. (Measured best: 16.0us)
// 1 float4 load -> 8 streaming (__stcs) stores; 1568 blocks x 512 threads.
// ---------------------------------------------------------------------------
__global__ void __launch_bounds__(512) bcast(float* __restrict__ out) {
    int gid  = blockIdx.x * 512 + threadIdx.x;    // 0 .. BATCH*32*S4-1
    int s4   = gid % S4;
    int rowg = gid / S4;                          // b*32 + cg
    int b    = rowg >> 5;
    int cg   = rowg & 31;

    float4 v = __ldg(reinterpret_cast<const float4*>(g_y) + b * S4 + s4);

    float4* p = reinterpret_cast<float4*>(out)
              + ((size_t)(b * CHAN + cg * 8)) * S4 + s4;
    #pragma unroll
    for (int k = 0; k < 8; ++k) {
        __stcs(p, v);                      // evict-first: don't churn L2
        p += S4;
    }
}

// ---------------------------------------------------------------------------
extern "C" void kernel_launch(void* const* d_in, const int* in_sizes, int n_in,
                              void* d_out, int out_size) {
    const float* x = (const float*)d_in[0];   // [32,256,56,56]
    const float* w = (const float*)d_in[1];   // [1,2,3,3]
    float* out = (float*)d_out;               // [32,256,56,56]

    pool_partial<<<(QSPLIT * BATCH * S4) / 256, 256>>>(x);   // 784 blocks
    mid_par<<<BATCH * MBLK, 1024>>>(w);                      // 128 blocks
    bcast<<<(BATCH * 32 * S4) / 512, 512>>>(out);            // 1568 blocks
}